// round 2
// baseline (speedup 1.0000x reference)
#include <cuda_runtime.h>
#include <math.h>

#define BATCH 2
#define SEQ 2048
#define DM 1024
#define NH 16
#define DH 64

// Scratch (device globals: allocation-free per harness rules)
__device__ float g_q[BATCH * SEQ * DM];
__device__ float g_k[BATCH * SEQ * DM];
__device__ float g_v[BATCH * SEQ * DM];
__device__ float g_z[BATCH * SEQ * DM];

// XOR swizzle for 64x64 fp32 smem tiles: conflict-free for row-vector and
// col-vector access patterns used below. addr = r*64 + (c ^ sw(r)),
// sw(r) = (r&31) ^ (r>>5) keeps bit5 information so 16 lanes reading
// 16 distinct rows at fixed c land in 16 distinct banks.
__device__ __forceinline__ int SWZ(int r, int c) {
    return r * 64 + (c ^ ((r ^ (r >> 5)) & 31));
}

// ---------------------------------------------------------------------------
// QKV projection: C[4096,1024] = X[4096,1024] @ W[h,d,e] (+bias[1024])
// blockIdx.z in {0,1,2} selects (X,W,b,C) for Q/K/V.
// Tile 64x64, K-tile 32, 256 threads, 4x4 per thread.
// ---------------------------------------------------------------------------
__global__ __launch_bounds__(256)
void qkv_gemm_kernel(const float* __restrict__ xq, const float* __restrict__ xk,
                     const float* __restrict__ xv,
                     const float* __restrict__ wq, const float* __restrict__ wk,
                     const float* __restrict__ wv,
                     const float* __restrict__ bq, const float* __restrict__ bk,
                     const float* __restrict__ bv)
{
    __shared__ float As[64 * 32];
    __shared__ float Bs[32 * 64];

    const int z = blockIdx.z;
    const float* __restrict__ X = (z == 0) ? xq : (z == 1) ? xk : xv;
    const float* __restrict__ W = (z == 0) ? wq : (z == 1) ? wk : wv;
    const float* __restrict__ B = (z == 0) ? bq : (z == 1) ? bk : bv;
    float* __restrict__ C       = (z == 0) ? g_q : (z == 1) ? g_k : g_v;

    const int t  = threadIdx.x;
    const int tx = t & 15;
    const int ty = t >> 4;
    const int m0 = blockIdx.y * 64;
    const int n0 = blockIdx.x * 64;

    // n0 is 64-aligned => entire N-tile is one head. W[h][k][e] rows stride 64.
    const int h = n0 >> 6;
    const float* __restrict__ Wb = W + (size_t)h * DM * DH;

    float acc[4][4] = {};

    for (int k0 = 0; k0 < DM; k0 += 32) {
        __syncthreads();
        // A tile 64x32 (coalesced rows of 32 floats)
        {
            int kk = t & 31, r = t >> 5;  // 8 rows per pass
            #pragma unroll
            for (int i = 0; i < 8; i++)
                As[(r + 8 * i) * 32 + kk] =
                    X[(size_t)(m0 + r + 8 * i) * DM + k0 + kk];
        }
        // B tile 32x64 (coalesced rows of 64 floats)
        {
            int n = t & 63, kr = t >> 6;  // 4 rows per pass
            #pragma unroll
            for (int i = 0; i < 8; i++)
                Bs[(kr + 4 * i) * 64 + n] =
                    Wb[(size_t)(k0 + kr + 4 * i) * DH + n];
        }
        __syncthreads();
        #pragma unroll
        for (int kk = 0; kk < 32; kk++) {
            float a0 = As[(ty * 4 + 0) * 32 + kk];
            float a1 = As[(ty * 4 + 1) * 32 + kk];
            float a2 = As[(ty * 4 + 2) * 32 + kk];
            float a3 = As[(ty * 4 + 3) * 32 + kk];
            float4 b = *(const float4*)&Bs[kk * 64 + tx * 4];
            acc[0][0] += a0 * b.x; acc[0][1] += a0 * b.y; acc[0][2] += a0 * b.z; acc[0][3] += a0 * b.w;
            acc[1][0] += a1 * b.x; acc[1][1] += a1 * b.y; acc[1][2] += a1 * b.z; acc[1][3] += a1 * b.w;
            acc[2][0] += a2 * b.x; acc[2][1] += a2 * b.y; acc[2][2] += a2 * b.z; acc[2][3] += a2 * b.w;
            acc[3][0] += a3 * b.x; acc[3][1] += a3 * b.y; acc[3][2] += a3 * b.z; acc[3][3] += a3 * b.w;
        }
    }

    #pragma unroll
    for (int i = 0; i < 4; i++) {
        int m = m0 + ty * 4 + i;
        #pragma unroll
        for (int j = 0; j < 4; j++) {
            int n = n0 + tx * 4 + j;
            C[(size_t)m * DM + n] = acc[i][j] + B[n];
        }
    }
}

// ---------------------------------------------------------------------------
// Output projection: out[4096,1024] = Z[4096,1024] @ W_O[1024,1024] + b_O
// W_O[h,e,d] reshapes to a plain row-major [1024,1024].
// ---------------------------------------------------------------------------
__global__ __launch_bounds__(256)
void out_gemm_kernel(const float* __restrict__ W, const float* __restrict__ bias,
                     float* __restrict__ C)
{
    __shared__ float As[64 * 32];
    __shared__ float Bs[32 * 64];

    const int t  = threadIdx.x;
    const int tx = t & 15;
    const int ty = t >> 4;
    const int m0 = blockIdx.y * 64;
    const int n0 = blockIdx.x * 64;
    const float* __restrict__ X  = g_z;
    const float* __restrict__ Wb = W + n0;

    float acc[4][4] = {};

    for (int k0 = 0; k0 < DM; k0 += 32) {
        __syncthreads();
        {
            int kk = t & 31, r = t >> 5;
            #pragma unroll
            for (int i = 0; i < 8; i++)
                As[(r + 8 * i) * 32 + kk] =
                    X[(size_t)(m0 + r + 8 * i) * DM + k0 + kk];
        }
        {
            int n = t & 63, kr = t >> 6;
            #pragma unroll
            for (int i = 0; i < 8; i++)
                Bs[(kr + 4 * i) * 64 + n] =
                    Wb[(size_t)(k0 + kr + 4 * i) * DM + n];
        }
        __syncthreads();
        #pragma unroll
        for (int kk = 0; kk < 32; kk++) {
            float a0 = As[(ty * 4 + 0) * 32 + kk];
            float a1 = As[(ty * 4 + 1) * 32 + kk];
            float a2 = As[(ty * 4 + 2) * 32 + kk];
            float a3 = As[(ty * 4 + 3) * 32 + kk];
            float4 b = *(const float4*)&Bs[kk * 64 + tx * 4];
            acc[0][0] += a0 * b.x; acc[0][1] += a0 * b.y; acc[0][2] += a0 * b.z; acc[0][3] += a0 * b.w;
            acc[1][0] += a1 * b.x; acc[1][1] += a1 * b.y; acc[1][2] += a1 * b.z; acc[1][3] += a1 * b.w;
            acc[2][0] += a2 * b.x; acc[2][1] += a2 * b.y; acc[2][2] += a2 * b.z; acc[2][3] += a2 * b.w;
            acc[3][0] += a3 * b.x; acc[3][1] += a3 * b.y; acc[3][2] += a3 * b.z; acc[3][3] += a3 * b.w;
        }
    }

    #pragma unroll
    for (int i = 0; i < 4; i++) {
        int m = m0 + ty * 4 + i;
        #pragma unroll
        for (int j = 0; j < 4; j++) {
            int n = n0 + tx * 4 + j;
            C[(size_t)m * DM + n] = acc[i][j] + bias[n];
        }
    }
}

// ---------------------------------------------------------------------------
// Causal flash attention (fp32, online softmax).
// Grid: (qblock=32, head=16, batch=2). Block: 256 threads.
// Q tile 64 rows resident; stream 64-key K/V tiles up to the diagonal.
// smem: Qs (64x64) + KPs (K tile, reused for P tile) + Vs = exactly 48 KB.
// Thread (tx,ty): score rows ty*4+[0,4), score cols (and out dims) tx*4+[0,4).
// ---------------------------------------------------------------------------
__global__ __launch_bounds__(256)
void attn_kernel()
{
    __shared__ float Qs[64 * 64];
    __shared__ float KPs[64 * 64];
    __shared__ float Vs[64 * 64];

    const int t  = threadIdx.x;
    const int tx = t & 15;
    const int ty = t >> 4;
    const int qb = blockIdx.x;
    const int h  = blockIdx.y;
    const int b  = blockIdx.z;
    const int q0 = qb * 64;

    // Load Q tile (swizzled)
    {
        int d = t & 63, r = t >> 6;
        #pragma unroll
        for (int i = 0; i < 16; i++) {
            int rr = r + 4 * i;
            Qs[SWZ(rr, d)] =
                g_q[(size_t)(b * SEQ + q0 + rr) * DM + h * DH + d];
        }
    }

    float acc[4][4] = {};
    float m_i[4], l_i[4];
    #pragma unroll
    for (int i = 0; i < 4; i++) { m_i[i] = -1e30f; l_i[i] = 0.0f; }

    const float scale = 0.125f;  // 1/sqrt(64)

    for (int kb = 0; kb <= qb; kb++) {
        const int k0 = kb * 64;
        __syncthreads();
        // Load K and V tiles (swizzled, coalesced)
        {
            int d = t & 63, r = t >> 6;
            #pragma unroll
            for (int i = 0; i < 16; i++) {
                int rr = r + 4 * i;
                size_t g = (size_t)(b * SEQ + k0 + rr) * DM + h * DH + d;
                KPs[SWZ(rr, d)] = g_k[g];
                Vs[SWZ(rr, d)]  = g_v[g];
            }
        }
        __syncthreads();

        // S = Q @ K^T (4x4 per thread)
        float s[4][4] = {};
        #pragma unroll 8
        for (int d = 0; d < 64; d++) {
            float a0 = Qs[SWZ(ty * 4 + 0, d)];
            float a1 = Qs[SWZ(ty * 4 + 1, d)];
            float a2 = Qs[SWZ(ty * 4 + 2, d)];
            float a3 = Qs[SWZ(ty * 4 + 3, d)];
            float c0 = KPs[SWZ(tx * 4 + 0, d)];
            float c1 = KPs[SWZ(tx * 4 + 1, d)];
            float c2 = KPs[SWZ(tx * 4 + 2, d)];
            float c3 = KPs[SWZ(tx * 4 + 3, d)];
            s[0][0] += a0 * c0; s[0][1] += a0 * c1; s[0][2] += a0 * c2; s[0][3] += a0 * c3;
            s[1][0] += a1 * c0; s[1][1] += a1 * c1; s[1][2] += a1 * c2; s[1][3] += a1 * c3;
            s[2][0] += a2 * c0; s[2][1] += a2 * c1; s[2][2] += a2 * c2; s[2][3] += a2 * c3;
            s[3][0] += a3 * c0; s[3][1] += a3 * c1; s[3][2] += a3 * c2; s[3][3] += a3 * c3;
        }

        // Scale + causal mask (only the diagonal tile has masked entries)
        #pragma unroll
        for (int i = 0; i < 4; i++) {
            int qg = q0 + ty * 4 + i;
            #pragma unroll
            for (int j = 0; j < 4; j++) {
                int kg = k0 + tx * 4 + j;
                float v = s[i][j] * scale;
                s[i][j] = (kg > qg) ? -1e9f : v;
            }
        }

        // Online softmax update (row groups = 16 lanes sharing ty)
        #pragma unroll
        for (int i = 0; i < 4; i++) {
            float mx = fmaxf(fmaxf(s[i][0], s[i][1]), fmaxf(s[i][2], s[i][3]));
            #pragma unroll
            for (int o = 8; o >= 1; o >>= 1)
                mx = fmaxf(mx, __shfl_xor_sync(0xffffffffu, mx, o, 16));
            float m_new = fmaxf(m_i[i], mx);
            float corr  = __expf(m_i[i] - m_new);
            m_i[i] = m_new;
            l_i[i] *= corr;
            #pragma unroll
            for (int j = 0; j < 4; j++) acc[i][j] *= corr;
            float rs = 0.0f;
            #pragma unroll
            for (int j = 0; j < 4; j++) {
                float p = __expf(s[i][j] - m_new);
                s[i][j] = p;
                rs += p;
            }
            #pragma unroll
            for (int o = 8; o >= 1; o >>= 1)
                rs += __shfl_xor_sync(0xffffffffu, rs, o, 16);
            l_i[i] += rs;
        }

        __syncthreads();  // all K reads complete before P overwrites KPs
        #pragma unroll
        for (int i = 0; i < 4; i++)
            #pragma unroll
            for (int j = 0; j < 4; j++)
                KPs[SWZ(ty * 4 + i, tx * 4 + j)] = s[i][j];
        __syncthreads();

        // acc += P @ V
        #pragma unroll 8
        for (int kc = 0; kc < 64; kc++) {
            float p0 = KPs[SWZ(ty * 4 + 0, kc)];
            float p1 = KPs[SWZ(ty * 4 + 1, kc)];
            float p2 = KPs[SWZ(ty * 4 + 2, kc)];
            float p3 = KPs[SWZ(ty * 4 + 3, kc)];
            float v0 = Vs[SWZ(kc, tx * 4 + 0)];
            float v1 = Vs[SWZ(kc, tx * 4 + 1)];
            float v2 = Vs[SWZ(kc, tx * 4 + 2)];
            float v3 = Vs[SWZ(kc, tx * 4 + 3)];
            acc[0][0] += p0 * v0; acc[0][1] += p0 * v1; acc[0][2] += p0 * v2; acc[0][3] += p0 * v3;
            acc[1][0] += p1 * v0; acc[1][1] += p1 * v1; acc[1][2] += p1 * v2; acc[1][3] += p1 * v3;
            acc[2][0] += p2 * v0; acc[2][1] += p2 * v1; acc[2][2] += p2 * v2; acc[2][3] += p2 * v3;
            acc[3][0] += p3 * v0; acc[3][1] += p3 * v1; acc[3][2] += p3 * v2; acc[3][3] += p3 * v3;
        }
    }

    // Normalize and store z[b, q, h, e]
    #pragma unroll
    for (int i = 0; i < 4; i++) {
        float inv = 1.0f / l_i[i];
        int q = q0 + ty * 4 + i;
        #pragma unroll
        for (int j = 0; j < 4; j++) {
            int d = tx * 4 + j;
            g_z[(size_t)(b * SEQ + q) * DM + h * DH + d] = acc[i][j] * inv;
        }
    }
}

// ---------------------------------------------------------------------------
extern "C" void kernel_launch(void* const* d_in, const int* in_sizes, int n_in,
                              void* d_out, int out_size)
{
    const float* qin = (const float*)d_in[0];
    const float* kin = (const float*)d_in[1];
    const float* vin = (const float*)d_in[2];
    const float* WQ  = (const float*)d_in[3];
    const float* WK  = (const float*)d_in[4];
    const float* WV  = (const float*)d_in[5];
    const float* WO  = (const float*)d_in[6];
    const float* bQ  = (const float*)d_in[7];
    const float* bK  = (const float*)d_in[8];
    const float* bV  = (const float*)d_in[9];
    const float* bO  = (const float*)d_in[10];
    float* out = (float*)d_out;

    dim3 gg(DM / 64, (BATCH * SEQ) / 64, 3);   // 16 x 64 x 3
    qkv_gemm_kernel<<<gg, 256>>>(qin, kin, vin, WQ, WK, WV, bQ, bK, bV);

    attn_kernel<<<dim3(SEQ / 64, NH, BATCH), 256>>>();

    dim3 go(DM / 64, (BATCH * SEQ) / 64);      // 16 x 64
    out_gemm_kernel<<<go, 256>>>(WO, bO, out);
}

// round 4
// speedup vs baseline: 1.9098x; 1.9098x over previous
#include <cuda_runtime.h>
#include <cuda_bf16.h>
#include <stdint.h>

#define BATCH 2
#define SEQ 2048
#define DM 1024
#define NH 16
#define DH 64
#define MTOT (BATCH*SEQ)
#define QSCALE 0.18033688f   // log2(e) / sqrt(64)

typedef __nv_bfloat16 bf16;

// ---------------- device-global scratch ----------------
__device__ __align__(16) bf16 g_xh[3ull*MTOT*DM], g_xl[3ull*MTOT*DM];
__device__ __align__(16) bf16 g_wth[3ull*DM*DM],  g_wtl[3ull*DM*DM];
__device__ __align__(16) bf16 g_woth[(size_t)DM*DM], g_wotl[(size_t)DM*DM];
__device__ __align__(16) bf16 g_qh[(size_t)MTOT*DM], g_ql[(size_t)MTOT*DM];
__device__ __align__(16) bf16 g_kh[(size_t)MTOT*DM], g_kl[(size_t)MTOT*DM];
__device__ __align__(16) bf16 g_vth[(size_t)MTOT*DM], g_vtl[(size_t)MTOT*DM]; // [bh*64+d][seq]
__device__ __align__(16) bf16 g_zh[(size_t)MTOT*DM], g_zl[(size_t)MTOT*DM];

// ---------------- helpers (baseline PTX only: ldmatrix + mma.sync) ----------------
__device__ __forceinline__ uint32_t smem_u32(const void* p) {
    uint32_t a;
    asm("{ .reg .u64 t; cvta.to.shared.u64 t, %1; cvt.u32.u64 %0, t; }" : "=r"(a) : "l"(p));
    return a;
}
#define SWZ128(o) ((o) ^ (((o) >> 3) & 0x70))

__device__ __forceinline__ void mma_bf16(float* c, const uint32_t* a, uint32_t b0, uint32_t b1) {
    asm volatile("mma.sync.aligned.m16n8k16.row.col.f32.bf16.bf16.f32 "
        "{%0,%1,%2,%3}, {%4,%5,%6,%7}, {%8,%9}, {%0,%1,%2,%3};"
        : "+f"(c[0]), "+f"(c[1]), "+f"(c[2]), "+f"(c[3])
        : "r"(a[0]), "r"(a[1]), "r"(a[2]), "r"(a[3]), "r"(b0), "r"(b1));
}
__device__ __forceinline__ void ldsm4(uint32_t* r, uint32_t a) {
    asm volatile("ldmatrix.sync.aligned.m8n8.x4.shared.b16 {%0,%1,%2,%3}, [%4];"
        : "=r"(r[0]), "=r"(r[1]), "=r"(r[2]), "=r"(r[3]) : "r"(a));
}
// x4 frag address: rows r0..r0+15, k-units ku,ku+1 (16B units), 128B rows, SW128
__device__ __forceinline__ uint32_t fraddr(uint32_t base, int lane, int r0, int ku) {
    int g = lane >> 3, r8 = lane & 7;
    return base + SWZ128(((r0 + r8 + ((g & 1) << 3)) << 7) + ((ku + (g >> 1)) << 4));
}
__device__ __forceinline__ float ex2f(float x) {
    float y; asm("ex2.approx.f32 %0, %1;" : "=f"(y) : "f"(x)); return y;
}
__device__ __forceinline__ void split2(float a, float b, uint32_t& hi, uint32_t& lo) {
    bf16 ah = __float2bfloat16(a), bh = __float2bfloat16(b);
    __nv_bfloat162 H; H.x = ah; H.y = bh;
    __nv_bfloat162 L;
    L.x = __float2bfloat16(a - __bfloat162float(ah));
    L.y = __float2bfloat16(b - __bfloat162float(bh));
    hi = *(uint32_t*)&H; lo = *(uint32_t*)&L;
}

// ---------------- conversion kernels ----------------
__global__ __launch_bounds__(256) void cvt_x_kernel(
    const float* __restrict__ q, const float* __restrict__ k, const float* __restrict__ v) {
    const int z = blockIdx.y;
    const float* __restrict__ src = (z == 0) ? q : (z == 1) ? k : v;
    size_t base = (size_t)z * MTOT * DM;
    size_t i = ((size_t)blockIdx.x * 256 + threadIdx.x) * 8;
    union { bf16 b[8]; uint4 u; } H, L;
    #pragma unroll
    for (int j = 0; j < 8; j += 4) {
        float4 f = *(const float4*)(src + i + j);
        float fv[4] = {f.x, f.y, f.z, f.w};
        #pragma unroll
        for (int q4 = 0; q4 < 4; q4++) {
            bf16 hh = __float2bfloat16(fv[q4]);
            H.b[j + q4] = hh;
            L.b[j + q4] = __float2bfloat16(fv[q4] - __bfloat162float(hh));
        }
    }
    *(uint4*)(g_xh + base + i) = H.u;
    *(uint4*)(g_xl + base + i) = L.u;
}

// W[w][h][k][e] -> g_wth[w][(h*64+e)][k]
__global__ __launch_bounds__(256) void cvt_wqkv_kernel(
    const float* __restrict__ wq, const float* __restrict__ wk, const float* __restrict__ wv) {
    __shared__ float s[32][33];
    const int w = blockIdx.z >> 4, hh = blockIdx.z & 15;
    const float* __restrict__ W = ((w == 0) ? wq : (w == 1) ? wk : wv) + (size_t)hh * DM * DH;
    const int k0 = blockIdx.x * 32, e0 = blockIdx.y * 32;
    const int tx = threadIdx.x, ty = threadIdx.y;
    #pragma unroll
    for (int i = 0; i < 4; i++)
        s[ty + 8 * i][tx] = W[(size_t)(k0 + ty + 8 * i) * DH + e0 + tx];
    __syncthreads();
    size_t dbase = (size_t)w * DM * DM;
    #pragma unroll
    for (int i = 0; i < 4; i++) {
        float v = s[tx][ty + 8 * i];
        bf16 hi = __float2bfloat16(v);
        size_t o = dbase + (size_t)(hh * 64 + e0 + ty + 8 * i) * DM + k0 + tx;
        g_wth[o] = hi;
        g_wtl[o] = __float2bfloat16(v - __bfloat162float(hi));
    }
}

// WO[k][d] -> g_woth[d][k]
__global__ __launch_bounds__(256) void cvt_wo_kernel(const float* __restrict__ W) {
    __shared__ float s[32][33];
    const int k0 = blockIdx.x * 32, d0 = blockIdx.y * 32;
    const int tx = threadIdx.x, ty = threadIdx.y;
    #pragma unroll
    for (int i = 0; i < 4; i++)
        s[ty + 8 * i][tx] = W[(size_t)(k0 + ty + 8 * i) * DM + d0 + tx];
    __syncthreads();
    #pragma unroll
    for (int i = 0; i < 4; i++) {
        float v = s[tx][ty + 8 * i];
        bf16 hi = __float2bfloat16(v);
        size_t o = (size_t)(d0 + ty + 8 * i) * DM + k0 + tx;
        g_woth[o] = hi;
        g_wotl[o] = __float2bfloat16(v - __bfloat162float(hi));
    }
}

// ---------------- split-bf16 mma.sync GEMM: C[128x128] = X @ Wt^T (+bias) ----------
// 256 threads (8 warps, grid 4x2: warp tile 32m x 64n). K-chunk 32.
// smem: A[128 rows][128B = hi(32k)|lo(32k)], B same. 32KB static.
// mode: 0=Q (scale, split out), 1=K (split out), 2=V (transposed split out), 3=fp32 out
__device__ __forceinline__ void proj_core(
    const bf16* __restrict__ Xh, const bf16* __restrict__ Xl,
    const bf16* __restrict__ Wh, const bf16* __restrict__ Wl,
    const float* __restrict__ bias,
    bf16* __restrict__ Oh, bf16* __restrict__ Ol, float* __restrict__ Of,
    char* sm, int m0, int n0, int mode)
{
    const int t = threadIdx.x, lane = t & 31, w = t >> 5;
    const uint32_t sb = smem_u32(sm);
    const int wm = (w & 3) * 32, wn = (w >> 2) * 64;
    float acc[2][8][4] = {};

    const int lr = t >> 1, ls = t & 1;
    const bf16* __restrict__ Ap = (ls ? Xl : Xh) + (size_t)(m0 + lr) * DM;
    const bf16* __restrict__ Bp = (ls ? Wl : Wh) + (size_t)(n0 + lr) * DM;
    uint32_t offA[4], offB[4];
    #pragma unroll
    for (int i = 0; i < 4; i++) {
        offA[i] = SWZ128((lr << 7) + ((ls * 4 + i) << 4));
        offB[i] = 16384 + SWZ128((lr << 7) + ((ls * 4 + i) << 4));
    }

    for (int kc = 0; kc < 32; kc++) {
        #pragma unroll
        for (int i = 0; i < 4; i++) {
            *(uint4*)(sm + offA[i]) = *(const uint4*)(Ap + kc * 32 + i * 8);
            *(uint4*)(sm + offB[i]) = *(const uint4*)(Bp + kc * 32 + i * 8);
        }
        __syncthreads();

        uint32_t aH[2][2][4], aL[2][2][4];
        #pragma unroll
        for (int mt = 0; mt < 2; mt++)
            #pragma unroll
            for (int ks = 0; ks < 2; ks++) {
                ldsm4(aH[mt][ks], fraddr(sb, lane, wm + mt * 16, 2 * ks));
                ldsm4(aL[mt][ks], fraddr(sb, lane, wm + mt * 16, 4 + 2 * ks));
            }
        #pragma unroll
        for (int ks = 0; ks < 2; ks++)
            #pragma unroll
            for (int np = 0; np < 4; np++) {
                uint32_t bH[4], bL[4];
                ldsm4(bH, fraddr(sb + 16384, lane, wn + np * 16, 2 * ks));
                ldsm4(bL, fraddr(sb + 16384, lane, wn + np * 16, 4 + 2 * ks));
                #pragma unroll
                for (int mt = 0; mt < 2; mt++) {
                    mma_bf16(acc[mt][2*np],   aH[mt][ks], bH[0], bH[2]);
                    mma_bf16(acc[mt][2*np+1], aH[mt][ks], bH[1], bH[3]);
                    mma_bf16(acc[mt][2*np],   aH[mt][ks], bL[0], bL[2]);
                    mma_bf16(acc[mt][2*np+1], aH[mt][ks], bL[1], bL[3]);
                    mma_bf16(acc[mt][2*np],   aL[mt][ks], bH[0], bH[2]);
                    mma_bf16(acc[mt][2*np+1], aL[mt][ks], bH[1], bH[3]);
                }
            }
        __syncthreads();
    }

    const float scale = (mode == 0) ? QSCALE : 1.0f;
    #pragma unroll
    for (int mt = 0; mt < 2; mt++)
        #pragma unroll
        for (int np = 0; np < 8; np++)
            #pragma unroll
            for (int h2 = 0; h2 < 2; h2++) {
                int m = m0 + wm + mt * 16 + (lane >> 2) + h2 * 8;
                int n = n0 + wn + np * 8 + 2 * (lane & 3);
                float v0 = (acc[mt][np][h2 * 2]     + bias[n])     * scale;
                float v1 = (acc[mt][np][h2 * 2 + 1] + bias[n + 1]) * scale;
                if (mode == 3) {
                    *(float2*)(Of + (size_t)m * DM + n) = make_float2(v0, v1);
                } else if (mode == 2) {
                    int bb = m >> 11, seq = m & 2047;
                    bf16 h0 = __float2bfloat16(v0), h1 = __float2bfloat16(v1);
                    size_t o0 = ((size_t)(bb * NH + (n >> 6)) * DH + (n & 63)) * SEQ + seq;
                    size_t o1 = ((size_t)(bb * NH + ((n+1) >> 6)) * DH + ((n+1) & 63)) * SEQ + seq;
                    Oh[o0] = h0; Ol[o0] = __float2bfloat16(v0 - __bfloat162float(h0));
                    Oh[o1] = h1; Ol[o1] = __float2bfloat16(v1 - __bfloat162float(h1));
                } else {
                    uint32_t hi, lo;
                    split2(v0, v1, hi, lo);
                    *(uint32_t*)(Oh + (size_t)m * DM + n) = hi;
                    *(uint32_t*)(Ol + (size_t)m * DM + n) = lo;
                }
            }
}

__global__ __launch_bounds__(256) void qkv_proj_mma(const float* bq, const float* bk,
                                                    const float* bv) {
    __shared__ __align__(128) char sm[32768];
    const int z = blockIdx.z;
    proj_core(g_xh + (size_t)z * MTOT * DM, g_xl + (size_t)z * MTOT * DM,
              g_wth + (size_t)z * DM * DM, g_wtl + (size_t)z * DM * DM,
              (z == 0) ? bq : (z == 1) ? bk : bv,
              (z == 0) ? g_qh : (z == 1) ? g_kh : g_vth,
              (z == 0) ? g_ql : (z == 1) ? g_kl : g_vtl,
              nullptr, sm, blockIdx.y * 128, blockIdx.x * 128, z);
}

__global__ __launch_bounds__(256) void out_proj_mma(const float* bo, float* out) {
    __shared__ __align__(128) char sm[32768];
    proj_core(g_zh, g_zl, g_woth, g_wotl, bo, nullptr, nullptr, out,
              sm, blockIdx.y * 128, blockIdx.x * 128, 3);
}

// ---------------- FA2-style attention (mma.sync, no-max softmax, causal) ----------
// CTA = (qb, head, batch), 256 threads, q-tile 128 (warp w owns rows 16w), key-tile 64.
// smem 64KB: QH@0 QL@16K KH@32K KL@40K VH@48K VL@56K
#define AQ_H 0
#define AQ_L 16384
#define AK_H 32768
#define AK_L 40960
#define AV_H 49152
#define AV_L 57344

__global__ __launch_bounds__(256) void attn_mma() {
    extern __shared__ char sm[];
    const uint32_t sb = smem_u32(sm);
    const int t = threadIdx.x, lane = t & 31, w = t >> 5;
    const int qb = blockIdx.x, hd = blockIdx.y, b = blockIdx.z;
    const int q0 = qb * 128, wq = w * 16;

    // load Q tile (128 rows x 64 d, hi/lo): 256 segs of 128B
    {
        int r = t >> 1, s = t & 1;
        const bf16* __restrict__ src =
            (s ? g_ql : g_qh) + (size_t)(b * SEQ + q0 + r) * DM + hd * DH;
        char* dst = sm + (s ? AQ_L : AQ_H);
        #pragma unroll
        for (int i = 0; i < 8; i++)
            *(uint4*)(dst + SWZ128((r << 7) + (i << 4))) = *(const uint4*)(src + i * 8);
    }
    __syncthreads();

    uint32_t qH[4][4], qL[4][4];
    #pragma unroll
    for (int ks = 0; ks < 4; ks++) {
        ldsm4(qH[ks], fraddr(sb + AQ_H, lane, wq, 2 * ks));
        ldsm4(qL[ks], fraddr(sb + AQ_L, lane, wq, 2 * ks));
    }
    __syncthreads();

    float oacc[8][4] = {};
    float lsum[2] = {0.0f, 0.0f};
    const int nkb = 2 * qb + 2;

    for (int kb = 0; kb < nkb; kb++) {
        const int k0 = kb * 64;
        // load K (64x64 hi/lo) + Vt (64x64 hi/lo): 256 segs x 128B
        {
            int isV = t >> 7, rr = (t >> 1) & 63, s = t & 1;
            const bf16* __restrict__ src;
            char* dst;
            if (!isV) {
                src = (s ? g_kl : g_kh) + (size_t)(b * SEQ + k0 + rr) * DM + hd * DH;
                dst = sm + (s ? AK_L : AK_H);
            } else {
                src = (s ? g_vtl : g_vth) + ((size_t)((b * NH + hd) * DH + rr)) * SEQ + k0;
                dst = sm + (s ? AV_L : AV_H);
            }
            #pragma unroll
            for (int i = 0; i < 8; i++)
                *(uint4*)(dst + SWZ128((rr << 7) + (i << 4))) = *(const uint4*)(src + i * 8);
        }
        __syncthreads();

        // S = Q K^T (3 split terms)
        float sacc[8][4] = {};
        #pragma unroll
        for (int ds = 0; ds < 4; ds++)
            #pragma unroll
            for (int np = 0; np < 4; np++) {
                uint32_t kH[4], kL[4];
                ldsm4(kH, fraddr(sb + AK_H, lane, np * 16, 2 * ds));
                ldsm4(kL, fraddr(sb + AK_L, lane, np * 16, 2 * ds));
                mma_bf16(sacc[2*np],   qH[ds], kH[0], kH[2]);
                mma_bf16(sacc[2*np+1], qH[ds], kH[1], kH[3]);
                mma_bf16(sacc[2*np],   qH[ds], kL[0], kL[2]);
                mma_bf16(sacc[2*np+1], qH[ds], kL[1], kL[3]);
                mma_bf16(sacc[2*np],   qL[ds], kH[0], kH[2]);
                mma_bf16(sacc[2*np+1], qL[ds], kH[1], kH[3]);
            }

        // mask + exp2 (scores already scaled by log2e/8 via Q)
        #pragma unroll
        for (int np = 0; np < 8; np++)
            #pragma unroll
            for (int j = 0; j < 4; j++) {
                int kg = k0 + np * 8 + 2 * (lane & 3) + (j & 1);
                int qg = q0 + wq + (lane >> 2) + (j >> 1) * 8;
                float p = (kg <= qg) ? ex2f(sacc[np][j]) : 0.0f;
                lsum[j >> 1] += p;
                sacc[np][j] = p;
            }

        // pack P (C-frag -> A-frag, split hi/lo) and PV mma per k-step
        #pragma unroll
        for (int ks = 0; ks < 4; ks++) {
            uint32_t pH[4], pL[4];
            split2(sacc[2*ks][0],   sacc[2*ks][1],   pH[0], pL[0]);
            split2(sacc[2*ks][2],   sacc[2*ks][3],   pH[1], pL[1]);
            split2(sacc[2*ks+1][0], sacc[2*ks+1][1], pH[2], pL[2]);
            split2(sacc[2*ks+1][2], sacc[2*ks+1][3], pH[3], pL[3]);
            #pragma unroll
            for (int dp = 0; dp < 4; dp++) {
                uint32_t vH[4], vL[4];
                ldsm4(vH, fraddr(sb + AV_H, lane, dp * 16, 2 * ks));
                ldsm4(vL, fraddr(sb + AV_L, lane, dp * 16, 2 * ks));
                mma_bf16(oacc[2*dp],   pH, vH[0], vH[2]);
                mma_bf16(oacc[2*dp+1], pH, vH[1], vH[3]);
                mma_bf16(oacc[2*dp],   pH, vL[0], vL[2]);
                mma_bf16(oacc[2*dp+1], pH, vL[1], vL[3]);
                mma_bf16(oacc[2*dp],   pL, vH[0], vH[2]);
                mma_bf16(oacc[2*dp+1], pL, vH[1], vH[3]);
            }
        }
        __syncthreads();
    }

    // l: quad reduce (lanes of a quad share the row)
    #pragma unroll
    for (int i = 0; i < 2; i++) {
        lsum[i] += __shfl_xor_sync(0xffffffffu, lsum[i], 1);
        lsum[i] += __shfl_xor_sync(0xffffffffu, lsum[i], 2);
    }
    float inv0 = 1.0f / lsum[0], inv1 = 1.0f / lsum[1];

    // z = O / l, split bf16, [b*SEQ+q][hd*64+d]
    #pragma unroll
    for (int np = 0; np < 8; np++)
        #pragma unroll
        for (int h2 = 0; h2 < 2; h2++) {
            int q = q0 + wq + (lane >> 2) + h2 * 8;
            int d = np * 8 + 2 * (lane & 3);
            float inv = h2 ? inv1 : inv0;
            float v0 = oacc[np][h2 * 2] * inv;
            float v1 = oacc[np][h2 * 2 + 1] * inv;
            uint32_t hi, lo;
            split2(v0, v1, hi, lo);
            size_t o = (size_t)(b * SEQ + q) * DM + hd * DH + d;
            *(uint32_t*)(g_zh + o) = hi;
            *(uint32_t*)(g_zl + o) = lo;
        }
}

// ---------------------------------------------------------------------------
extern "C" void kernel_launch(void* const* d_in, const int* in_sizes, int n_in,
                              void* d_out, int out_size)
{
    const float* qin = (const float*)d_in[0];
    const float* kin = (const float*)d_in[1];
    const float* vin = (const float*)d_in[2];
    const float* WQ  = (const float*)d_in[3];
    const float* WK  = (const float*)d_in[4];
    const float* WV  = (const float*)d_in[5];
    const float* WO  = (const float*)d_in[6];
    const float* bQ  = (const float*)d_in[7];
    const float* bK  = (const float*)d_in[8];
    const float* bV  = (const float*)d_in[9];
    const float* bO  = (const float*)d_in[10];
    float* out = (float*)d_out;

    cudaFuncSetAttribute(attn_mma, cudaFuncAttributeMaxDynamicSharedMemorySize, 65536);

    cvt_x_kernel<<<dim3(MTOT * DM / 8 / 256, 3), 256>>>(qin, kin, vin);
    cvt_wqkv_kernel<<<dim3(32, 2, 48), dim3(32, 8)>>>(WQ, WK, WV);
    cvt_wo_kernel<<<dim3(32, 32), dim3(32, 8)>>>(WO);

    qkv_proj_mma<<<dim3(DM / 128, MTOT / 128, 3), 256>>>(bQ, bK, bV);
    attn_mma<<<dim3(SEQ / 128, NH, BATCH), 256, 65536>>>();
    out_proj_mma<<<dim3(DM / 128, MTOT / 128), 256>>>(bO, out);
}

// round 5
// speedup vs baseline: 3.6594x; 1.9161x over previous
#include <cuda_runtime.h>
#include <cuda_bf16.h>
#include <stdint.h>

#define BATCH 2
#define SEQ 2048
#define DM 1024
#define NH 16
#define DH 64
#define MTOT (BATCH*SEQ)
#define QSCALE 0.18033688f   // log2(e) / sqrt(64)

typedef __nv_bfloat16 bf16;

// ---------------- device-global scratch ----------------
__device__ __align__(16) bf16 g_xh[3ull*MTOT*DM], g_xl[3ull*MTOT*DM];
__device__ __align__(16) bf16 g_wth[3ull*DM*DM],  g_wtl[3ull*DM*DM];
__device__ __align__(16) bf16 g_woth[(size_t)DM*DM], g_wotl[(size_t)DM*DM];
__device__ __align__(16) bf16 g_qh[(size_t)MTOT*DM], g_ql[(size_t)MTOT*DM];
__device__ __align__(16) bf16 g_kh[(size_t)MTOT*DM], g_kl[(size_t)MTOT*DM];
__device__ __align__(16) bf16 g_vth[(size_t)MTOT*DM], g_vtl[(size_t)MTOT*DM]; // [bh*64+d][seq]
__device__ __align__(16) bf16 g_zh[(size_t)MTOT*DM], g_zl[(size_t)MTOT*DM];

// ---------------- helpers ----------------
__device__ __forceinline__ uint32_t smem_u32(const void* p) {
    uint32_t a;
    asm("{ .reg .u64 t; cvta.to.shared.u64 t, %1; cvt.u32.u64 %0, t; }" : "=r"(a) : "l"(p));
    return a;
}
#define SWZ128(o) ((o) ^ (((o) >> 3) & 0x70))

__device__ __forceinline__ void mma_bf16(float* c, const uint32_t* a, uint32_t b0, uint32_t b1) {
    asm volatile("mma.sync.aligned.m16n8k16.row.col.f32.bf16.bf16.f32 "
        "{%0,%1,%2,%3}, {%4,%5,%6,%7}, {%8,%9}, {%0,%1,%2,%3};"
        : "+f"(c[0]), "+f"(c[1]), "+f"(c[2]), "+f"(c[3])
        : "r"(a[0]), "r"(a[1]), "r"(a[2]), "r"(a[3]), "r"(b0), "r"(b1));
}
__device__ __forceinline__ void ldsm4(uint32_t* r, uint32_t a) {
    asm volatile("ldmatrix.sync.aligned.m8n8.x4.shared.b16 {%0,%1,%2,%3}, [%4];"
        : "=r"(r[0]), "=r"(r[1]), "=r"(r[2]), "=r"(r[3]) : "r"(a));
}
// x4 frag address: rows r0..r0+15, 16B-units ku,ku+1; 128B rows, SW128
__device__ __forceinline__ uint32_t fraddr(uint32_t base, int lane, int r0, int ku) {
    int g = lane >> 3, r8 = lane & 7;
    return base + SWZ128(((r0 + r8 + ((g & 1) << 3)) << 7) + ((ku + (g >> 1)) << 4));
}
__device__ __forceinline__ float ex2f(float x) {
    float y; asm("ex2.approx.f32 %0, %1;" : "=f"(y) : "f"(x)); return y;
}
__device__ __forceinline__ void split2(float a, float b, uint32_t& hi, uint32_t& lo) {
    bf16 ah = __float2bfloat16(a), bh = __float2bfloat16(b);
    __nv_bfloat162 H; H.x = ah; H.y = bh;
    __nv_bfloat162 L;
    L.x = __float2bfloat16(a - __bfloat162float(ah));
    L.y = __float2bfloat16(b - __bfloat162float(bh));
    hi = *(uint32_t*)&H; lo = *(uint32_t*)&L;
}
__device__ __forceinline__ void cpa16(uint32_t dst, const void* src) {
    asm volatile("cp.async.cg.shared.global [%0], [%1], 16;" :: "r"(dst), "l"(src) : "memory");
}
#define CP_COMMIT() asm volatile("cp.async.commit_group;" ::: "memory")
#define CP_WAIT(n)  asm volatile("cp.async.wait_group %0;" :: "n"(n) : "memory")

// ---------------- conversion kernels ----------------
__global__ __launch_bounds__(256) void cvt_x_kernel(
    const float* __restrict__ q, const float* __restrict__ k, const float* __restrict__ v) {
    const int z = blockIdx.y;
    const float* __restrict__ src = (z == 0) ? q : (z == 1) ? k : v;
    size_t base = (size_t)z * MTOT * DM;
    size_t i = ((size_t)blockIdx.x * 256 + threadIdx.x) * 8;
    union { bf16 b[8]; uint4 u; } H, L;
    #pragma unroll
    for (int j = 0; j < 8; j += 4) {
        float4 f = *(const float4*)(src + i + j);
        float fv[4] = {f.x, f.y, f.z, f.w};
        #pragma unroll
        for (int q4 = 0; q4 < 4; q4++) {
            bf16 hh = __float2bfloat16(fv[q4]);
            H.b[j + q4] = hh;
            L.b[j + q4] = __float2bfloat16(fv[q4] - __bfloat162float(hh));
        }
    }
    *(uint4*)(g_xh + base + i) = H.u;
    *(uint4*)(g_xl + base + i) = L.u;
}

// W[w][h][k][e] -> g_wth[w][(h*64+e)][k]
__global__ __launch_bounds__(256) void cvt_wqkv_kernel(
    const float* __restrict__ wq, const float* __restrict__ wk, const float* __restrict__ wv) {
    __shared__ float s[32][33];
    const int w = blockIdx.z >> 4, hh = blockIdx.z & 15;
    const float* __restrict__ W = ((w == 0) ? wq : (w == 1) ? wk : wv) + (size_t)hh * DM * DH;
    const int k0 = blockIdx.x * 32, e0 = blockIdx.y * 32;
    const int tx = threadIdx.x, ty = threadIdx.y;
    #pragma unroll
    for (int i = 0; i < 4; i++)
        s[ty + 8 * i][tx] = W[(size_t)(k0 + ty + 8 * i) * DH + e0 + tx];
    __syncthreads();
    size_t dbase = (size_t)w * DM * DM;
    #pragma unroll
    for (int i = 0; i < 4; i++) {
        float v = s[tx][ty + 8 * i];
        bf16 hi = __float2bfloat16(v);
        size_t o = dbase + (size_t)(hh * 64 + e0 + ty + 8 * i) * DM + k0 + tx;
        g_wth[o] = hi;
        g_wtl[o] = __float2bfloat16(v - __bfloat162float(hi));
    }
}

// WO[k][d] -> g_woth[d][k]
__global__ __launch_bounds__(256) void cvt_wo_kernel(const float* __restrict__ W) {
    __shared__ float s[32][33];
    const int k0 = blockIdx.x * 32, d0 = blockIdx.y * 32;
    const int tx = threadIdx.x, ty = threadIdx.y;
    #pragma unroll
    for (int i = 0; i < 4; i++)
        s[ty + 8 * i][tx] = W[(size_t)(k0 + ty + 8 * i) * DM + d0 + tx];
    __syncthreads();
    #pragma unroll
    for (int i = 0; i < 4; i++) {
        float v = s[tx][ty + 8 * i];
        bf16 hi = __float2bfloat16(v);
        size_t o = (size_t)(d0 + ty + 8 * i) * DM + k0 + tx;
        g_woth[o] = hi;
        g_wotl[o] = __float2bfloat16(v - __bfloat162float(hi));
    }
}

// ---------------- split-bf16 mma.sync GEMM with cp.async pipeline ----------------
// C[128x128] = X @ Wt^T (+bias). 256 threads (8 warps, 4x2; warp tile 32m x 64n).
// K-chunk 64. Stage (64KB): A_hi@0 A_lo@16K B_hi@32K B_lo@48K. 2 stages = 128KB dynamic.
#define PJ_STAGE 65536

__device__ __forceinline__ void proj_copy(
    const bf16* __restrict__ Xh, const bf16* __restrict__ Xl,
    const bf16* __restrict__ Wh, const bf16* __restrict__ Wl,
    uint32_t sb, int st, int m0, int n0, int k0, int t)
{
    #pragma unroll
    for (int u = 0; u < 8; u++) {
        int idx = u * 256 + t;
        int sp = idx >> 10, row = (idx >> 3) & 127, c = idx & 7;
        uint32_t so = SWZ128((row << 7) + (c << 4));
        cpa16(sb + st + sp * 16384 + so,
              (sp ? Xl : Xh) + (size_t)(m0 + row) * DM + k0 + c * 8);
        cpa16(sb + st + 32768 + sp * 16384 + so,
              (sp ? Wl : Wh) + (size_t)(n0 + row) * DM + k0 + c * 8);
    }
}

__device__ __forceinline__ void proj_compute(uint32_t sb, int st, int lane,
                                             int wm, int wn, float acc[2][8][4])
{
    #pragma unroll
    for (int ks = 0; ks < 4; ks++) {
        uint32_t aH[2][4], aL[2][4];
        #pragma unroll
        for (int mt = 0; mt < 2; mt++) {
            ldsm4(aH[mt], fraddr(sb + st,         lane, wm + mt * 16, 2 * ks));
            ldsm4(aL[mt], fraddr(sb + st + 16384, lane, wm + mt * 16, 2 * ks));
        }
        #pragma unroll
        for (int np = 0; np < 4; np++) {
            uint32_t bH[4], bL[4];
            ldsm4(bH, fraddr(sb + st + 32768, lane, wn + np * 16, 2 * ks));
            ldsm4(bL, fraddr(sb + st + 49152, lane, wn + np * 16, 2 * ks));
            #pragma unroll
            for (int mt = 0; mt < 2; mt++) {
                mma_bf16(acc[mt][2*np],   aH[mt], bH[0], bH[2]);
                mma_bf16(acc[mt][2*np+1], aH[mt], bH[1], bH[3]);
                mma_bf16(acc[mt][2*np],   aH[mt], bL[0], bL[2]);
                mma_bf16(acc[mt][2*np+1], aH[mt], bL[1], bL[3]);
                mma_bf16(acc[mt][2*np],   aL[mt], bH[0], bH[2]);
                mma_bf16(acc[mt][2*np+1], aL[mt], bH[1], bH[3]);
            }
        }
    }
}

// mode: 0=Q (scale, split out), 1=K (split out), 2=V (transposed split out), 3=fp32 out
__device__ __forceinline__ void proj_core(
    const bf16* __restrict__ Xh, const bf16* __restrict__ Xl,
    const bf16* __restrict__ Wh, const bf16* __restrict__ Wl,
    const float* __restrict__ bias,
    bf16* __restrict__ Oh, bf16* __restrict__ Ol, float* __restrict__ Of,
    char* sm, int m0, int n0, int mode)
{
    const int t = threadIdx.x, lane = t & 31, w = t >> 5;
    const uint32_t sb = smem_u32(sm);
    const int wm = (w & 3) * 32, wn = (w >> 2) * 64;
    float acc[2][8][4] = {};

    proj_copy(Xh, Xl, Wh, Wl, sb, 0, m0, n0, 0, t);
    CP_COMMIT();

    for (int kc = 0; kc < 16; kc++) {
        if (kc + 1 < 16) {
            proj_copy(Xh, Xl, Wh, Wl, sb, ((kc + 1) & 1) * PJ_STAGE, m0, n0, (kc + 1) * 64, t);
            CP_COMMIT();
            CP_WAIT(1);
        } else {
            CP_WAIT(0);
        }
        __syncthreads();
        proj_compute(sb, (kc & 1) * PJ_STAGE, lane, wm, wn, acc);
        __syncthreads();
    }

    const float scale = (mode == 0) ? QSCALE : 1.0f;
    #pragma unroll
    for (int mt = 0; mt < 2; mt++)
        #pragma unroll
        for (int np = 0; np < 8; np++)
            #pragma unroll
            for (int h2 = 0; h2 < 2; h2++) {
                int m = m0 + wm + mt * 16 + (lane >> 2) + h2 * 8;
                int n = n0 + wn + np * 8 + 2 * (lane & 3);
                float v0 = (acc[mt][np][h2 * 2]     + bias[n])     * scale;
                float v1 = (acc[mt][np][h2 * 2 + 1] + bias[n + 1]) * scale;
                if (mode == 3) {
                    *(float2*)(Of + (size_t)m * DM + n) = make_float2(v0, v1);
                } else if (mode == 2) {
                    int bb = m >> 11, seq = m & 2047;
                    bf16 h0 = __float2bfloat16(v0), h1 = __float2bfloat16(v1);
                    size_t o0 = ((size_t)(bb * NH + (n >> 6)) * DH + (n & 63)) * SEQ + seq;
                    size_t o1 = ((size_t)(bb * NH + ((n+1) >> 6)) * DH + ((n+1) & 63)) * SEQ + seq;
                    Oh[o0] = h0; Ol[o0] = __float2bfloat16(v0 - __bfloat162float(h0));
                    Oh[o1] = h1; Ol[o1] = __float2bfloat16(v1 - __bfloat162float(h1));
                } else {
                    uint32_t hi, lo;
                    split2(v0, v1, hi, lo);
                    *(uint32_t*)(Oh + (size_t)m * DM + n) = hi;
                    *(uint32_t*)(Ol + (size_t)m * DM + n) = lo;
                }
            }
}

__global__ __launch_bounds__(256, 1) void qkv_proj_mma(const float* bq, const float* bk,
                                                       const float* bv) {
    extern __shared__ char sm[];
    const int z = blockIdx.z;
    proj_core(g_xh + (size_t)z * MTOT * DM, g_xl + (size_t)z * MTOT * DM,
              g_wth + (size_t)z * DM * DM, g_wtl + (size_t)z * DM * DM,
              (z == 0) ? bq : (z == 1) ? bk : bv,
              (z == 0) ? g_qh : (z == 1) ? g_kh : g_vth,
              (z == 0) ? g_ql : (z == 1) ? g_kl : g_vtl,
              nullptr, sm, blockIdx.y * 128, blockIdx.x * 128, z);
}

__global__ __launch_bounds__(256, 1) void out_proj_mma(const float* bo, float* out) {
    extern __shared__ char sm[];
    proj_core(g_zh, g_zl, g_woth, g_wotl, bo, nullptr, nullptr, out,
              sm, blockIdx.y * 128, blockIdx.x * 128, 3);
}

// ---------------- FA2-style attention with cp.async K/V pipeline ----------------
// CTA = (qb, head, batch), 256 threads, q-tile 128 (warp w owns rows 16w), key-tile 64.
// smem: Q_hi@0 Q_lo@16K; stages at 32K + s*32K: K_hi@0 K_lo@8K V_hi@16K V_lo@24K. 96KB.
#define AT_STAGE0 32768
#define AT_STRIDE 32768

__device__ __forceinline__ void attn_copy(uint32_t sb, int kb, int b, int hd, int t) {
    const int st = AT_STAGE0 + (kb & 1) * AT_STRIDE;
    const int k0 = kb * 64;
    #pragma unroll
    for (int u = 0; u < 4; u++) {
        int idx = u * 256 + t;
        int sp = idx >> 9, row = (idx >> 3) & 63, c = idx & 7;
        uint32_t so = SWZ128((row << 7) + (c << 4));
        cpa16(sb + st + sp * 8192 + so,
              (sp ? g_kl : g_kh) + (size_t)(b * SEQ + k0 + row) * DM + hd * DH + c * 8);
        cpa16(sb + st + 16384 + sp * 8192 + so,
              (sp ? g_vtl : g_vth) + ((size_t)((b * NH + hd) * DH + row)) * SEQ + k0 + c * 8);
    }
}

__global__ __launch_bounds__(256, 1) void attn_mma() {
    extern __shared__ char sm[];
    const uint32_t sb = smem_u32(sm);
    const int t = threadIdx.x, lane = t & 31, w = t >> 5;
    const int qb = blockIdx.x, hd = blockIdx.y, b = blockIdx.z;
    const int q0 = qb * 128, wq = w * 16;
    const int nkb = 2 * qb + 2;

    attn_copy(sb, 0, b, hd, t);
    CP_COMMIT();

    // load Q tile (128 rows x 64 d, hi/lo) via plain stores
    {
        int r = t >> 1, s = t & 1;
        const bf16* __restrict__ src =
            (s ? g_ql : g_qh) + (size_t)(b * SEQ + q0 + r) * DM + hd * DH;
        char* dst = sm + (s ? 16384 : 0);
        #pragma unroll
        for (int i = 0; i < 8; i++)
            *(uint4*)(dst + SWZ128((r << 7) + (i << 4))) = *(const uint4*)(src + i * 8);
    }
    __syncthreads();

    uint32_t qH[4][4], qL[4][4];
    #pragma unroll
    for (int ks = 0; ks < 4; ks++) {
        ldsm4(qH[ks], fraddr(sb,         lane, wq, 2 * ks));
        ldsm4(qL[ks], fraddr(sb + 16384, lane, wq, 2 * ks));
    }

    float oacc[8][4] = {};
    float lsum[2] = {0.0f, 0.0f};

    for (int kb = 0; kb < nkb; kb++) {
        const int k0 = kb * 64;
        const int st = AT_STAGE0 + (kb & 1) * AT_STRIDE;
        if (kb + 1 < nkb) {
            attn_copy(sb, kb + 1, b, hd, t);
            CP_COMMIT();
            CP_WAIT(1);
        } else {
            CP_WAIT(0);
        }
        __syncthreads();

        // S = Q K^T (3 split terms)
        float sacc[8][4] = {};
        #pragma unroll
        for (int ds = 0; ds < 4; ds++)
            #pragma unroll
            for (int np = 0; np < 4; np++) {
                uint32_t kH[4], kL[4];
                ldsm4(kH, fraddr(sb + st,        lane, np * 16, 2 * ds));
                ldsm4(kL, fraddr(sb + st + 8192, lane, np * 16, 2 * ds));
                mma_bf16(sacc[2*np],   qH[ds], kH[0], kH[2]);
                mma_bf16(sacc[2*np+1], qH[ds], kH[1], kH[3]);
                mma_bf16(sacc[2*np],   qH[ds], kL[0], kL[2]);
                mma_bf16(sacc[2*np+1], qH[ds], kL[1], kL[3]);
                mma_bf16(sacc[2*np],   qL[ds], kH[0], kH[2]);
                mma_bf16(sacc[2*np+1], qL[ds], kH[1], kH[3]);
            }

        // mask + exp2 (scores pre-scaled by log2e/8 via Q epilogue)
        if (kb >= 2 * qb) {
            #pragma unroll
            for (int np = 0; np < 8; np++)
                #pragma unroll
                for (int j = 0; j < 4; j++) {
                    int kg = k0 + np * 8 + 2 * (lane & 3) + (j & 1);
                    int qg = q0 + wq + (lane >> 2) + (j >> 1) * 8;
                    float p = (kg <= qg) ? ex2f(sacc[np][j]) : 0.0f;
                    lsum[j >> 1] += p;
                    sacc[np][j] = p;
                }
        } else {
            #pragma unroll
            for (int np = 0; np < 8; np++)
                #pragma unroll
                for (int j = 0; j < 4; j++) {
                    float p = ex2f(sacc[np][j]);
                    lsum[j >> 1] += p;
                    sacc[np][j] = p;
                }
        }

        // P (C-frag -> A-frag split) and PV
        #pragma unroll
        for (int ks = 0; ks < 4; ks++) {
            uint32_t pH[4], pL[4];
            split2(sacc[2*ks][0],   sacc[2*ks][1],   pH[0], pL[0]);
            split2(sacc[2*ks][2],   sacc[2*ks][3],   pH[1], pL[1]);
            split2(sacc[2*ks+1][0], sacc[2*ks+1][1], pH[2], pL[2]);
            split2(sacc[2*ks+1][2], sacc[2*ks+1][3], pH[3], pL[3]);
            #pragma unroll
            for (int dp = 0; dp < 4; dp++) {
                uint32_t vH[4], vL[4];
                ldsm4(vH, fraddr(sb + st + 16384, lane, dp * 16, 2 * ks));
                ldsm4(vL, fraddr(sb + st + 24576, lane, dp * 16, 2 * ks));
                mma_bf16(oacc[2*dp],   pH, vH[0], vH[2]);
                mma_bf16(oacc[2*dp+1], pH, vH[1], vH[3]);
                mma_bf16(oacc[2*dp],   pH, vL[0], vL[2]);
                mma_bf16(oacc[2*dp+1], pH, vL[1], vL[3]);
                mma_bf16(oacc[2*dp],   pL, vH[0], vH[2]);
                mma_bf16(oacc[2*dp+1], pL, vH[1], vH[3]);
            }
        }
        __syncthreads();
    }

    // l: quad reduce (lanes of a quad share the row)
    #pragma unroll
    for (int i = 0; i < 2; i++) {
        lsum[i] += __shfl_xor_sync(0xffffffffu, lsum[i], 1);
        lsum[i] += __shfl_xor_sync(0xffffffffu, lsum[i], 2);
    }
    float inv0 = 1.0f / lsum[0], inv1 = 1.0f / lsum[1];

    // z = O / l, split bf16, [b*SEQ+q][hd*64+d]
    #pragma unroll
    for (int np = 0; np < 8; np++)
        #pragma unroll
        for (int h2 = 0; h2 < 2; h2++) {
            int q = q0 + wq + (lane >> 2) + h2 * 8;
            int d = np * 8 + 2 * (lane & 3);
            float inv = h2 ? inv1 : inv0;
            float v0 = oacc[np][h2 * 2] * inv;
            float v1 = oacc[np][h2 * 2 + 1] * inv;
            uint32_t hi, lo;
            split2(v0, v1, hi, lo);
            size_t o = (size_t)(b * SEQ + q) * DM + hd * DH + d;
            *(uint32_t*)(g_zh + o) = hi;
            *(uint32_t*)(g_zl + o) = lo;
        }
}

// ---------------------------------------------------------------------------
extern "C" void kernel_launch(void* const* d_in, const int* in_sizes, int n_in,
                              void* d_out, int out_size)
{
    const float* qin = (const float*)d_in[0];
    const float* kin = (const float*)d_in[1];
    const float* vin = (const float*)d_in[2];
    const float* WQ  = (const float*)d_in[3];
    const float* WK  = (const float*)d_in[4];
    const float* WV  = (const float*)d_in[5];
    const float* WO  = (const float*)d_in[6];
    const float* bQ  = (const float*)d_in[7];
    const float* bK  = (const float*)d_in[8];
    const float* bV  = (const float*)d_in[9];
    const float* bO  = (const float*)d_in[10];
    float* out = (float*)d_out;

    cudaFuncSetAttribute(qkv_proj_mma, cudaFuncAttributeMaxDynamicSharedMemorySize, 131072);
    cudaFuncSetAttribute(out_proj_mma, cudaFuncAttributeMaxDynamicSharedMemorySize, 131072);
    cudaFuncSetAttribute(attn_mma,     cudaFuncAttributeMaxDynamicSharedMemorySize, 98304);

    cvt_x_kernel<<<dim3(MTOT * DM / 8 / 256, 3), 256>>>(qin, kin, vin);
    cvt_wqkv_kernel<<<dim3(32, 2, 48), dim3(32, 8)>>>(WQ, WK, WV);
    cvt_wo_kernel<<<dim3(32, 32), dim3(32, 8)>>>(WO);

    qkv_proj_mma<<<dim3(DM / 128, MTOT / 128, 3), 256, 131072>>>(bQ, bK, bV);
    attn_mma<<<dim3(SEQ / 128, NH, BATCH), 256, 98304>>>();
    out_proj_mma<<<dim3(DM / 128, MTOT / 128), 256, 131072>>>(bO, out);
}